// round 16
// baseline (speedup 1.0000x reference)
#include <cuda_runtime.h>
#include <cstdint>

// Problem constants
#define TT   16
#define BB   512
#define NIN  3072
#define SS1  256
#define SS2  256
#define SS3  128
#define EE   8
#define DECAYF 0.95f
#define KCHUNK 512   // confirmed reference k-partition: 512-chunks, serial ascending fold
#define MM   (TT * BB)   // 8192

typedef unsigned long long ull;

// Persistent scratch (allocation-free: __device__ globals)
__device__ float g_H1[(size_t)EE * MM * SS1];   // 67 MB
__device__ float g_H2[(size_t)EE * MM * SS2];   // 67 MB
__device__ float g_H3[(size_t)EE * MM * SS3];   // 33 MB
__device__ float g_C1[(size_t)MM * SS1];        // 8.4 MB  (row-major [m][o])
__device__ float g_C2[(size_t)MM * SS2];        // 8.4 MB
__device__ float g_Xt [(size_t)NIN * MM];       // 100 MB  X transposed [k][m]
__device__ float g_C1t[(size_t)SS1 * MM];       // 8.4 MB
__device__ float g_C2t[(size_t)SS2 * MM];       // 8.4 MB
__device__ float g_W1t[(size_t)EE * NIN * SS1]; // 25 MB   W1 transposed [e][k][n]
__device__ float g_W2t[(size_t)EE * SS1 * SS2]; // 2 MB
__device__ float g_W3t[(size_t)EE * SS2 * SS3]; // 1 MB

// ---- packed f32x2 helpers: each half is an independent rn op, bit-exact
//      vs the scalar serial chain (verified rel_err==0.0 since R11) -------
__device__ __forceinline__ ull fma2(ull a, ull b, ull c) {
    asm("fma.rn.f32x2 %0, %1, %2, %0;" : "+l"(c) : "l"(a), "l"(b));
    return c;
}
__device__ __forceinline__ ull add2(ull a, ull b) {
    ull r; asm("add.rn.f32x2 %0, %1, %2;" : "=l"(r) : "l"(a), "l"(b));
    return r;
}
__device__ __forceinline__ ull dup2(float x) {
    ull r; asm("mov.b64 %0, {%1, %1};" : "=l"(r) : "f"(x));
    return r;
}
__device__ __forceinline__ float2 unpk(ull a) {
    float2 r; asm("mov.b64 {%0, %1}, %2;" : "=f"(r.x), "=f"(r.y) : "l"(a));
    return r;
}
__device__ __forceinline__ void cpa16(uint32_t s, const void* g) {
    asm volatile("cp.async.ca.shared.global [%0], [%1], 16;" :: "r"(s), "l"(g));
}

// ---------------------------------------------------------------------------
// Batched transpose: src[z][R][C] -> dst[z][C][R]. 32x32 tiles, 32x8 threads.
// R, C multiples of 32.
// ---------------------------------------------------------------------------
__global__ void transpose_b(const float* __restrict__ src,
                            float* __restrict__ dst, int R, int C) {
    __shared__ float t[32][33];
    const float* s = src + (size_t)blockIdx.z * R * C;
    float*       d = dst + (size_t)blockIdx.z * R * C;
    int c0 = blockIdx.x * 32, r0 = blockIdx.y * 32;
    int x = threadIdx.x, y = threadIdx.y;
    #pragma unroll
    for (int i = 0; i < 32; i += 8)
        t[y + i][x] = s[(size_t)(r0 + y + i) * C + c0 + x];
    __syncthreads();
    #pragma unroll
    for (int i = 0; i < 32; i += 8)
        d[(size_t)(c0 + y + i) * R + r0 + x] = t[x][y + i];
}

// ---------------------------------------------------------------------------
// Batched NT SGEMM from k-major inputs, packed f32x2, k-chunked (PC=512)
// fp32 accumulation with REGISTER chunk fold:
//   per chunk: fresh accumulator accP, strictly ascending rn-FMA chain;
//   at each chunk boundary accC = rn(accC + accP) (accC starts 0; first
//   fold exact). Final store: rn(accC + accP) (exact no-op additions when
//   a fold just happened / when accC==0 for K<PC). Bit-identical to the
//   confirmed reference partition.
// Xt: [K][M] float.  Wt: [E][K][N] float.
// BM=64, BN=128, BK=32, 256 threads.
// Accumulator packs COLUMN pairs: thread (ty,tx) owns rows ty*4..ty*4+3 and
// cols tx*8..tx*8+7 as 4 ull pairs -> W operands are natural contiguous
// (w_{2j},w_{2j+1}) pairs: 2x LDS.128 from unduplicated W smem.
// X operands (x,x) come from a per-warp dup scratch filled ONCE per tile
// (8 LDS + 8 STS.64 per thread per tile), read as 2 broadcast LDS.128.
// Inner kk: 4 LDS + 16 fma2, zero MOVs.
// Ring-3 cp.async pipeline (24KB/stage) + 16KB dup scratch = 88KB smem.
// M%64==0, N%128==0, K%32==0, PC%32==0.
// ---------------------------------------------------------------------------
__global__ void __launch_bounds__(256, 2) gemm_f32x2(
    const float* __restrict__ Xt,  // [K][M]
    const float* __restrict__ Wt,  // [E][K][N]
    float* __restrict__ H,         // [E][M][N]
    int M, int N, int K, int PC)
{
    const int BK = 32, BM = 64, BN = 128;
    extern __shared__ float smem[];   // ring: 3 x 6144 floats; dup: 2048 ull
    const uint32_t sb = (uint32_t)__cvta_generic_to_shared(smem);

    const int e  = blockIdx.z;
    const int m0 = blockIdx.x * BM;
    const int n0 = blockIdx.y * BN;
    float* Hp = H + (size_t)e * M * N;

    const int tid  = threadIdx.x;
    const int wid  = tid >> 5, lane = tid & 31;
    const int ty   = tid >> 4;           // 0..15: rows ty*4 .. ty*4+3
    const int tx   = tid & 15;           // 0..15: cols tx*8 .. tx*8+7
    ull* Xd = reinterpret_cast<ull*>(smem + 3 * 6144) + wid * 256; // [kk][r] r=0..7

    ull accP[4][4], accC[4][4];
    #pragma unroll
    for (int i = 0; i < 4; i++)
        #pragma unroll
        for (int j = 0; j < 4; j++) { accP[i][j] = 0ULL; accC[i][j] = 0ULL; }

    // cp.async one BK-tile (X 8KB + W 16KB) into ring stage s.
    auto copy_tile = [&](int k0, int s) {
        uint32_t xs = sb + (uint32_t)s * 24576;
        uint32_t ws = xs + 8192;
        const float* xsrc = Xt + (size_t)k0 * M + m0;
        #pragma unroll
        for (int i = 0; i < 2; i++) {                 // 512 granules of 16B
            int g  = tid + i * 256;
            int kk = g >> 4, mc = (g & 15) << 2;
            cpa16(xs + (uint32_t)(kk * BM + mc) * 4, xsrc + (size_t)kk * M + mc);
        }
        const float* wsrc = Wt + ((size_t)e * K + k0) * N + n0;
        #pragma unroll
        for (int i = 0; i < 4; i++) {                 // 1024 granules of 16B
            int g  = tid + i * 256;
            int kk = g >> 5, nc = (g & 31) << 2;
            cpa16(ws + (uint32_t)(kk * BN + nc) * 4, wsrc + (size_t)kk * N + nc);
        }
        asm volatile("cp.async.commit_group;");
    };

    const int nt = K / BK;
    copy_tile(0, 0);
    if (nt > 1) copy_tile(BK, 1);

    for (int i = 0; i < nt; i++) {
        const int k0 = i * BK;
        if (i < nt - 1) asm volatile("cp.async.wait_group 1;");
        else            asm volatile("cp.async.wait_group 0;");
        __syncthreads();   // tile i visible; all warps done with stage (i+2)%3
        if (i + 2 < nt) copy_tile(k0 + 2 * BK, (i + 2) % 3);

        const float* Xb = smem + (i % 3) * 6144;        // 32 x 64 floats
        const float* Wb = Xb + 2048;                    // 32 x 128 floats

        // Per-warp X duplication: rows wid*8..wid*8+7, all 32 k.
        #pragma unroll
        for (int q = 0; q < 8; q++) {
            int idx = lane + 32 * q;                    // 256 entries
            int kk = idx >> 3, r = idx & 7;
            Xd[idx] = dup2(Xb[kk * BM + wid * 8 + r]);
        }
        __syncwarp();

        #pragma unroll
        for (int kk = 0; kk < BK; kk++) {   // strictly ascending k
            ull xp[4], wp[4];
            const ull* xr = Xd + kk * 8 + (ty & 1) * 4;  // broadcast LDS.128 x2
            xp[0] = xr[0]; xp[1] = xr[1]; xp[2] = xr[2]; xp[3] = xr[3];
            const ull* wr = reinterpret_cast<const ull*>(Wb + kk * BN + tx * 8);
            wp[0] = wr[0]; wp[1] = wr[1]; wp[2] = wr[2]; wp[3] = wr[3]; // LDS.128 x2
            #pragma unroll
            for (int ii = 0; ii < 4; ii++)
                #pragma unroll
                for (int j = 0; j < 4; j++)
                    accP[ii][j] = fma2(xp[ii], wp[j], accP[ii][j]);
        }

        // 512-chunk boundary: fold into accC (serial ascending), reset accP.
        if (((k0 + BK) % PC) == 0) {
            #pragma unroll
            for (int ii = 0; ii < 4; ii++)
                #pragma unroll
                for (int j = 0; j < 4; j++) {
                    accC[ii][j] = add2(accC[ii][j], accP[ii][j]);
                    accP[ii][j] = 0ULL;
                }
        }
        __syncwarp();      // warp done reading Xd before next tile's dup
    }

    // Epilogue: final = accC + accP. Exact no-op add when accP==0 (fold just
    // happened) or accC==0 (K < PC single-chain case).
    #pragma unroll
    for (int ii = 0; ii < 4; ii++) {
        float o[8];
        #pragma unroll
        for (int j = 0; j < 4; j++) {
            float2 r = unpk(add2(accC[ii][j], accP[ii][j]));
            o[2*j] = r.x; o[2*j+1] = r.y;               // adjacent columns
        }
        float* a = &Hp[(size_t)(m0 + ty * 4 + ii) * N + n0 + tx * 8];
        *reinterpret_cast<float4*>(a)     = make_float4(o[0], o[1], o[2], o[3]);
        *reinterpret_cast<float4*>(a + 4) = make_float4(o[4], o[5], o[6], o[7]);
    }
}

// ---------------------------------------------------------------------------
// LIF scan over ALL timesteps, 4 elements per thread (float4 path).
//   v = rn(rn(v*0.95) + h) ; spk = (v>=1) ; v = rn(v - spk)
//   c = sum_e g[e]*spk ;  mean = (sum_t c) * 1/16  (both exact)
// ---------------------------------------------------------------------------
__global__ void lif_scan4(
    const float* __restrict__ H,    // [E][M][no]
    const float* __restrict__ g,
    float* __restrict__ Cout,       // [M][no] (null: skip)
    float* __restrict__ Omean,      // [B*no]
    int no)
{
    int n = BB * no;
    int i4 = (blockIdx.x * blockDim.x + threadIdx.x) * 4;
    if (i4 >= n) return;
    float gv[EE];
    #pragma unroll
    for (int e = 0; e < EE; e++) gv[e] = __ldg(&g[e]);
    float v[EE][4];
    #pragma unroll
    for (int e = 0; e < EE; e++)
        #pragma unroll
        for (int u = 0; u < 4; u++) v[e][u] = 0.f;
    float osum[4] = {0.f, 0.f, 0.f, 0.f};

    for (int t = 0; t < TT; t++) {
        float c[4] = {0.f, 0.f, 0.f, 0.f};
        #pragma unroll
        for (int e = 0; e < EE; e++) {
            float4 h = *reinterpret_cast<const float4*>(
                &H[((size_t)e * MM + (size_t)t * BB) * no + i4]);
            float hv[4] = {h.x, h.y, h.z, h.w};
            #pragma unroll
            for (int u = 0; u < 4; u++) {
                float vv  = __fadd_rn(__fmul_rn(v[e][u], DECAYF), hv[u]);
                float spk = (vv >= 1.0f) ? 1.0f : 0.0f;
                v[e][u] = __fsub_rn(vv, spk);
                c[u] = __fadd_rn(c[u], __fmul_rn(gv[e], spk));
            }
        }
        if (Cout)
            *reinterpret_cast<float4*>(&Cout[(size_t)t * n + i4]) =
                make_float4(c[0], c[1], c[2], c[3]);
        #pragma unroll
        for (int u = 0; u < 4; u++) osum[u] = __fadd_rn(osum[u], c[u]);
    }
    *reinterpret_cast<float4*>(&Omean[i4]) = make_float4(
        __fmul_rn(osum[0], 1.0f/(float)TT), __fmul_rn(osum[1], 1.0f/(float)TT),
        __fmul_rn(osum[2], 1.0f/(float)TT), __fmul_rn(osum[3], 1.0f/(float)TT));
}

// ---------------------------------------------------------------------------
extern "C" void kernel_launch(void* const* d_in, const int* in_sizes, int n_in,
                              void* d_out, int out_size) {
    const float* X  = (const float*)d_in[0];  // [16][512][3072]
    const float* W1 = (const float*)d_in[1];  // [8][256][3072]
    const float* W2 = (const float*)d_in[2];  // [8][256][256]
    const float* W3 = (const float*)d_in[3];  // [8][128][256]
    const float* g1 = (const float*)d_in[4];
    const float* g2 = (const float*)d_in[5];
    const float* g3 = (const float*)d_in[6];
    float* out = (float*)d_out;

    float *H1, *H2, *H3, *C1, *C2, *Xt, *C1t, *C2t, *W1t, *W2t, *W3t;
    cudaGetSymbolAddress((void**)&H1,  g_H1);
    cudaGetSymbolAddress((void**)&H2,  g_H2);
    cudaGetSymbolAddress((void**)&H3,  g_H3);
    cudaGetSymbolAddress((void**)&C1,  g_C1);
    cudaGetSymbolAddress((void**)&C2,  g_C2);
    cudaGetSymbolAddress((void**)&Xt,  g_Xt);
    cudaGetSymbolAddress((void**)&C1t, g_C1t);
    cudaGetSymbolAddress((void**)&C2t, g_C2t);
    cudaGetSymbolAddress((void**)&W1t, g_W1t);
    cudaGetSymbolAddress((void**)&W2t, g_W2t);
    cudaGetSymbolAddress((void**)&W3t, g_W3t);

    const int SMEM = 3 * 24576 + 16384;   // 88 KB dynamic (ring + dup scratch)
    static bool attr_set = false;
    if (!attr_set) {
        cudaFuncSetAttribute(gemm_f32x2,
            cudaFuncAttributeMaxDynamicSharedMemorySize, SMEM);
        attr_set = true;
    }

    const int n1 = BB * SS1, n2 = BB * SS2, n3 = BB * SS3;
    dim3 tb(32, 8);

    // ---- Stage 1 ----
    transpose_b<<<dim3(NIN/32, MM/32, 1),   tb>>>(X,  Xt,  MM,  NIN);
    transpose_b<<<dim3(NIN/32, SS1/32, EE), tb>>>(W1, W1t, SS1, NIN);
    gemm_f32x2<<<dim3(MM/64, SS1/128, EE), 256, SMEM>>>(Xt, W1t, H1, MM, SS1, NIN, KCHUNK);
    lif_scan4<<<(n1/4 + 255)/256, 256>>>(H1, g1, C1, out, SS1);

    // ---- Stage 2 ----
    transpose_b<<<dim3(SS1/32, MM/32, 1),   tb>>>(C1, C1t, MM,  SS1);
    transpose_b<<<dim3(SS1/32, SS2/32, EE), tb>>>(W2, W2t, SS2, SS1);
    gemm_f32x2<<<dim3(MM/64, SS2/128, EE), 256, SMEM>>>(C1t, W2t, H2, MM, SS2, SS1, KCHUNK);
    lif_scan4<<<(n2/4 + 255)/256, 256>>>(H2, g2, C2, out + n1, SS2);

    // ---- Stage 3 ----
    transpose_b<<<dim3(SS2/32, MM/32, 1),   tb>>>(C2, C2t, MM,  SS2);
    transpose_b<<<dim3(SS2/32, SS3/32, EE), tb>>>(W3, W3t, SS3, SS2);
    gemm_f32x2<<<dim3(MM/64, SS3/128, EE), 256, SMEM>>>(C2t, W3t, H3, MM, SS3, SS2, KCHUNK);
    lif_scan4<<<(n3/4 + 255)/256, 256>>>(H3, g3, nullptr, out + n1 + n2, SS3);
}